// round 1
// baseline (speedup 1.0000x reference)
#include <cuda_runtime.h>
#include <math.h>

#define BDIM 256
#define SDIM 1024
#define DDIM 32
#define KDIM 512
// D * (log(STD) + 0.5*log(2*pi)) with STD=1, D=32  -> 16*log(2*pi)
#define LOG_NORM 29.406033062549525f

// Scratch (device globals; no allocation allowed)
__device__ float g_c[BDIM * KDIM];   // c[b,k] = log_mix - 0.5*m2 - log_norm
__device__ float g_maxc[BDIM];       // max_k c[b,k]
__device__ float g_maxmu;            // max_k ||mu_k||

// ---------------------------------------------------------------------------
// Kernel A: per-batch preprocessing. Grid = B blocks, 512 threads (one per k).
// Computes log_softmax of logits[b,:], m2[k], c[b,k], maxc[b], maxmu.
// ---------------------------------------------------------------------------
__global__ void prep_kernel(const float* __restrict__ logits,
                            const float* __restrict__ means) {
    __shared__ float red[KDIM];
    const int b = blockIdx.x;
    const int k = threadIdx.x;

    const float lg = logits[b * KDIM + k];

    // --- block max of logits ---
    red[k] = lg;
    __syncthreads();
    #pragma unroll
    for (int o = KDIM / 2; o > 0; o >>= 1) {
        if (k < o) red[k] = fmaxf(red[k], red[k + o]);
        __syncthreads();
    }
    const float maxl = red[0];
    __syncthreads();

    // --- block sum of exp(lg - maxl) ---
    red[k] = __expf(lg - maxl);
    __syncthreads();
    #pragma unroll
    for (int o = KDIM / 2; o > 0; o >>= 1) {
        if (k < o) red[k] = red[k] + red[k + o];
        __syncthreads();
    }
    const float lse = maxl + logf(red[0]);
    __syncthreads();

    // --- m2[k] = ||mu_k||^2 (vectorized row read) ---
    const float4* mr = (const float4*)(means + (size_t)k * DDIM);
    float m2 = 0.0f;
    #pragma unroll
    for (int i = 0; i < DDIM / 4; i++) {
        float4 v = mr[i];
        m2 += v.x * v.x + v.y * v.y + v.z * v.z + v.w * v.w;
    }

    const float c = lg - lse - 0.5f * m2 - LOG_NORM;
    g_c[b * KDIM + k] = c;

    // --- block max of c ---
    red[k] = c;
    __syncthreads();
    #pragma unroll
    for (int o = KDIM / 2; o > 0; o >>= 1) {
        if (k < o) red[k] = fmaxf(red[k], red[k + o]);
        __syncthreads();
    }
    if (k == 0) g_maxc[b] = red[0];
    __syncthreads();

    // --- block max of m2 -> maxmu (same value written by every block; benign) ---
    red[k] = m2;
    __syncthreads();
    #pragma unroll
    for (int o = KDIM / 2; o > 0; o >>= 1) {
        if (k < o) red[k] = fmaxf(red[k], red[k + o]);
        __syncthreads();
    }
    if (k == 0) g_maxmu = sqrtf(red[0]);
}

// ---------------------------------------------------------------------------
// Kernel B: fused dot + logsumexp. One thread per (b,s) row.
// Block = 256 threads -> 256 consecutive s values of one b.
// Grid = B * (S/256) = 1024 blocks.
// means staged into smem in 2 chunks of 256 components (32 KB each).
// ---------------------------------------------------------------------------
#define KCHUNK 256

__global__ __launch_bounds__(256) void nll_kernel(const float* __restrict__ x,
                                                  const float* __restrict__ means,
                                                  float* __restrict__ out) {
    __shared__ float s_mu[KCHUNK * DDIM];   // 32 KB
    __shared__ float s_c[KCHUNK];           // 1 KB

    const int b = blockIdx.x >> 2;          // S/256 = 4 tiles
    const int stile = blockIdx.x & 3;
    const int t = threadIdx.x;
    const int s = stile * 256 + t;

    // Load this thread's x row (32 floats) into registers
    const float4* xr = (const float4*)(x + ((size_t)b * SDIM + s) * DDIM);
    float4 xv[8];
    #pragma unroll
    for (int i = 0; i < 8; i++) xv[i] = xr[i];

    float x2 = 0.0f;
    #pragma unroll
    for (int i = 0; i < 8; i++)
        x2 += xv[i].x * xv[i].x + xv[i].y * xv[i].y +
              xv[i].z * xv[i].z + xv[i].w * xv[i].w;

    const float M = g_maxc[b] + sqrtf(x2) * g_maxmu;   // safe upper bound on z_k

    float sum = 0.0f;

    for (int chunk = 0; chunk < KDIM / KCHUNK; chunk++) {
        __syncthreads();
        // Stage 256 component rows: thread t loads row (chunk*256 + t)
        {
            const float4* mr =
                (const float4*)(means + ((size_t)chunk * KCHUNK + t) * DDIM);
            float4* sm = (float4*)s_mu;
            #pragma unroll
            for (int i = 0; i < 8; i++) sm[t * 8 + i] = mr[i];
            s_c[t] = g_c[b * KDIM + chunk * KCHUNK + t];
        }
        __syncthreads();

        #pragma unroll 4
        for (int k = 0; k < KCHUNK; k++) {
            const float4* m = (const float4*)(s_mu + k * DDIM);
            float d0 = 0.0f, d1 = 0.0f, d2 = 0.0f, d3 = 0.0f;
            #pragma unroll
            for (int i = 0; i < 8; i += 4) {
                float4 m0 = m[i + 0], m1 = m[i + 1], m2v = m[i + 2], m3 = m[i + 3];
                d0 += xv[i + 0].x * m0.x + xv[i + 0].y * m0.y +
                      xv[i + 0].z * m0.z + xv[i + 0].w * m0.w;
                d1 += xv[i + 1].x * m1.x + xv[i + 1].y * m1.y +
                      xv[i + 1].z * m1.z + xv[i + 1].w * m1.w;
                d2 += xv[i + 2].x * m2v.x + xv[i + 2].y * m2v.y +
                      xv[i + 2].z * m2v.z + xv[i + 2].w * m2v.w;
                d3 += xv[i + 3].x * m3.x + xv[i + 3].y * m3.y +
                      xv[i + 3].z * m3.z + xv[i + 3].w * m3.w;
            }
            const float dot = (d0 + d1) + (d2 + d3);
            sum += __expf(s_c[k] + dot - M);
        }
    }

    out[(size_t)b * SDIM + s] = 0.5f * x2 - M - __logf(sum);
}

// ---------------------------------------------------------------------------
extern "C" void kernel_launch(void* const* d_in, const int* in_sizes, int n_in,
                              void* d_out, int out_size) {
    const float* x      = (const float*)d_in[0];   // [256,1024,32]
    const float* logits = (const float*)d_in[1];   // [256,512]
    const float* means  = (const float*)d_in[2];   // [512,32]
    float* out = (float*)d_out;                    // [256,1024]

    prep_kernel<<<BDIM, KDIM>>>(logits, means);
    nll_kernel<<<BDIM * (SDIM / 256), 256>>>(x, means, out);
}

// round 7
// speedup vs baseline: 6.0708x; 6.0708x over previous
#include <cuda_runtime.h>
#include <cuda_bf16.h>
#include <math.h>
#include <stdint.h>

#define BDIM 256
#define SDIM 1024
#define DDIM 32
#define KDIM 512
// D * (log(STD) + 0.5*log(2*pi)) with STD=1, D=32  -> 16*log(2*pi)
#define LOG_NORM 29.406033062549525f
#define L2E 1.4426950408889634f

// Scratch (device globals; no allocation allowed)
__device__ float g_w[BDIM * KDIM];   // w[b,k] = exp(c[b,k])
__device__ float g_maxc[BDIM];       // max_k c[b,k]
__device__ float g_maxmu;            // max_k ||mu_k||
// means in mma.sync B-fragment order: [ntile(64)][kstep(2)][lane(32)] -> uint2{b0,b1}
__device__ uint2 g_bfrag[64 * 2 * 32];

__device__ __forceinline__ float ex2f(float a) {
    float r;
    asm("ex2.approx.ftz.f32 %0, %1;" : "=f"(r) : "f"(a));
    return r;
}

__device__ __forceinline__ uint32_t pack_bf16x2(float lo, float hi) {
    uint32_t l = (uint32_t)__bfloat16_as_ushort(__float2bfloat16_rn(lo));
    uint32_t h = (uint32_t)__bfloat16_as_ushort(__float2bfloat16_rn(hi));
    return (h << 16) | l;
}

// m16n8k16 bf16 MMA, f32 accumulate (sm_80+ PTX; no sm_103a-only features)
__device__ __forceinline__ void mma16816(float& c0, float& c1, float& c2, float& c3,
                                         uint32_t a0, uint32_t a1, uint32_t a2, uint32_t a3,
                                         uint32_t b0, uint32_t b1) {
    asm volatile(
        "mma.sync.aligned.m16n8k16.row.col.f32.bf16.bf16.f32 "
        "{%0,%1,%2,%3}, {%4,%5,%6,%7}, {%8,%9}, {%0,%1,%2,%3};"
        : "+f"(c0), "+f"(c1), "+f"(c2), "+f"(c3)
        : "r"(a0), "r"(a1), "r"(a2), "r"(a3), "r"(b0), "r"(b1));
}

// ---------------------------------------------------------------------------
// Kernel A: per-batch preprocessing (unchanged, validated in R1).
// ---------------------------------------------------------------------------
__global__ void prep_kernel(const float* __restrict__ logits,
                            const float* __restrict__ means) {
    __shared__ float red[KDIM];
    const int b = blockIdx.x;
    const int k = threadIdx.x;

    const float lg = logits[b * KDIM + k];

    red[k] = lg;
    __syncthreads();
    #pragma unroll
    for (int o = KDIM / 2; o > 0; o >>= 1) {
        if (k < o) red[k] = fmaxf(red[k], red[k + o]);
        __syncthreads();
    }
    const float maxl = red[0];
    __syncthreads();

    red[k] = __expf(lg - maxl);
    __syncthreads();
    #pragma unroll
    for (int o = KDIM / 2; o > 0; o >>= 1) {
        if (k < o) red[k] = red[k] + red[k + o];
        __syncthreads();
    }
    const float lse = maxl + logf(red[0]);
    __syncthreads();

    const float4* mr = (const float4*)(means + (size_t)k * DDIM);
    float m2 = 0.0f;
    #pragma unroll
    for (int i = 0; i < DDIM / 4; i++) {
        float4 v = mr[i];
        m2 += v.x * v.x + v.y * v.y + v.z * v.z + v.w * v.w;
    }

    const float c = lg - lse - 0.5f * m2 - LOG_NORM;
    g_w[b * KDIM + k] = expf(c);

    red[k] = c;
    __syncthreads();
    #pragma unroll
    for (int o = KDIM / 2; o > 0; o >>= 1) {
        if (k < o) red[k] = fmaxf(red[k], red[k + o]);
        __syncthreads();
    }
    if (k == 0) g_maxc[b] = red[0];
    __syncthreads();

    red[k] = m2;
    __syncthreads();
    #pragma unroll
    for (int o = KDIM / 2; o > 0; o >>= 1) {
        if (k < o) red[k] = fmaxf(red[k], red[k + o]);
        __syncthreads();
    }
    if (k == 0) g_maxmu = sqrtf(red[0]);
}

// ---------------------------------------------------------------------------
// Kernel A2: build means B-fragments once. 4096 threads, one entry each.
// Entry e = (j*2 + s)*32 + lane; n = j*8 + lane/4; k = s*16 + (lane%4)*2.
// b0 = bf16x2(means[n][k], means[n][k+1]); b1 = same at k+8.
// ---------------------------------------------------------------------------
__global__ void frag_kernel(const float* __restrict__ means) {
    const int e = blockIdx.x * 256 + threadIdx.x;   // 0..4095
    const int l = e & 31;
    const int s = (e >> 5) & 1;
    const int j = e >> 6;
    const int n = j * 8 + (l >> 2);
    const int k = s * 16 + (l & 3) * 2;
    const float* mp = means + n * DDIM + k;
    uint2 f;
    f.x = pack_bf16x2(mp[0], mp[1]);
    f.y = pack_bf16x2(mp[8], mp[9]);
    g_bfrag[e] = f;
}

// ---------------------------------------------------------------------------
// Kernel B: mma.sync GEMM + fused logsumexp epilogue.
// CTA = 128 s-rows of one b; warp w owns rows w*16..w*16+15, all K=512.
// Grid = B * (S/128) = 2048 CTAs, 256 threads.
// ---------------------------------------------------------------------------
#define PITCH 36    // bf16 elems per staged x row (72 B) -> conflict-dodging pitch

__global__ __launch_bounds__(256) void nll_hmma(const float* __restrict__ x,
                                                float* __restrict__ out) {
    __shared__ float s_w[KDIM];                     // 2 KB
    __shared__ float s_M[128];
    __shared__ float s_x2[128];
    __shared__ __nv_bfloat16 s_xbf[128 * PITCH];    // 9216 B
    __shared__ uint2 s_bf[64 * 2 * 32];             // 32 KB

    const int tid = threadIdx.x;
    const int wid = tid >> 5;
    const int lane = tid & 31;
    const int b = blockIdx.x >> 3;                  // S/128 = 8 tiles
    const int tile = blockIdx.x & 7;

    // mixture weights
    s_w[tid]       = g_w[b * KDIM + tid];
    s_w[tid + 256] = g_w[b * KDIM + tid + 256];

    // copy B-fragments (32 KB, coalesced uint4)
    {
        const uint4* src = (const uint4*)g_bfrag;   // 2048 uint4
        uint4* dst = (uint4*)s_bf;
        #pragma unroll
        for (int i = 0; i < 8; i++) dst[tid + i * 256] = src[tid + i * 256];
    }

    if (tid < 128) {
        // stage this thread's x row (fp32 -> bf16) + x2 + M
        const float4* xr =
            (const float4*)(x + ((size_t)b * SDIM + tile * 128 + tid) * DDIM);
        float x2 = 0.0f;
        #pragma unroll
        for (int i = 0; i < 8; i++) {
            float4 v = xr[i];
            x2 += v.x * v.x + v.y * v.y + v.z * v.z + v.w * v.w;
            uint32_t p0 = pack_bf16x2(v.x, v.y);
            uint32_t p1 = pack_bf16x2(v.z, v.w);
            uint32_t* dp = (uint32_t*)&s_xbf[tid * PITCH + i * 4];
            dp[0] = p0;
            dp[1] = p1;
        }
        s_x2[tid] = x2;
        s_M[tid] = g_maxc[b] + sqrtf(x2) * g_maxmu;
    }
    __syncthreads();

    // ---- A fragments: rows r0 = wid*16 + lane/4 and r0+8, 2 k-steps ----
    const int r0 = wid * 16 + (lane >> 2);
    const int kq = (lane & 3) * 2;
    uint32_t a[8];
    #pragma unroll
    for (int s = 0; s < 2; s++) {
        const int kb = s * 16 + kq;
        a[s * 4 + 0] = *(const uint32_t*)&s_xbf[r0 * PITCH + kb];
        a[s * 4 + 1] = *(const uint32_t*)&s_xbf[(r0 + 8) * PITCH + kb];
        a[s * 4 + 2] = *(const uint32_t*)&s_xbf[r0 * PITCH + kb + 8];
        a[s * 4 + 3] = *(const uint32_t*)&s_xbf[(r0 + 8) * PITCH + kb + 8];
    }

    const float M0 = s_M[r0];
    const float M1 = s_M[r0 + 8];
    const float nM0 = -M0 * L2E;
    const float nM1 = -M1 * L2E;
    float acc0 = 0.0f, acc1 = 0.0f;

    #pragma unroll 4
    for (int j = 0; j < 64; j++) {
        const uint2 bf0 = s_bf[(j * 2 + 0) * 32 + lane];
        const uint2 bf1 = s_bf[(j * 2 + 1) * 32 + lane];
        float c0 = 0.0f, c1 = 0.0f, c2 = 0.0f, c3 = 0.0f;
        mma16816(c0, c1, c2, c3, a[0], a[1], a[2], a[3], bf0.x, bf0.y);
        mma16816(c0, c1, c2, c3, a[4], a[5], a[6], a[7], bf1.x, bf1.y);
        // columns n0 = j*8 + kq, n0+1  (c0,c1 -> row r0; c2,c3 -> row r0+8)
        const float2 wv = *(const float2*)&s_w[j * 8 + kq];
        acc0 = fmaf(wv.x, ex2f(fmaf(c0, L2E, nM0)), acc0);
        acc0 = fmaf(wv.y, ex2f(fmaf(c1, L2E, nM0)), acc0);
        acc1 = fmaf(wv.x, ex2f(fmaf(c2, L2E, nM1)), acc1);
        acc1 = fmaf(wv.y, ex2f(fmaf(c3, L2E, nM1)), acc1);
    }

    // quad reduction (lanes 4g..4g+3 share rows)
    acc0 += __shfl_xor_sync(0xFFFFFFFFu, acc0, 1);
    acc0 += __shfl_xor_sync(0xFFFFFFFFu, acc0, 2);
    acc1 += __shfl_xor_sync(0xFFFFFFFFu, acc1, 1);
    acc1 += __shfl_xor_sync(0xFFFFFFFFu, acc1, 2);

    if ((lane & 3) == 0) {
        const size_t obase = (size_t)b * SDIM + tile * 128;
        out[obase + r0]     = 0.5f * s_x2[r0]     - M0 - logf(acc0);
        out[obase + r0 + 8] = 0.5f * s_x2[r0 + 8] - M1 - logf(acc1);
    }
}

// ---------------------------------------------------------------------------
extern "C" void kernel_launch(void* const* d_in, const int* in_sizes, int n_in,
                              void* d_out, int out_size) {
    const float* x      = (const float*)d_in[0];   // [256,1024,32]
    const float* logits = (const float*)d_in[1];   // [256,512]
    const float* means  = (const float*)d_in[2];   // [512,32]
    float* out = (float*)d_out;                    // [256,1024]

    prep_kernel<<<BDIM, KDIM>>>(logits, means);
    frag_kernel<<<16, 256>>>(means);
    nll_hmma<<<BDIM * (SDIM / 128), 256>>>(x, out);
}